// round 6
// baseline (speedup 1.0000x reference)
#include <cuda_runtime.h>
#include <cstdint>

// PDHG L1 solver: x = sh(x - a*A^T u, a); u += b*(A(2x_new - x_old) - b_vec)
// bs=32, m=256, n=512, iters=1000, alpha=beta=0.02
//
// Design: 32 clusters of 4 CTAs (one cluster per batch, 128 CTAs = 1 wave).
// Each CTA owns 64 rows of A: SMEM row-major copy (for A*y phase) + a
// register-resident column copy a[64] per thread (for A^T*u phase).
// u is partitioned across the cluster (64 entries per CTA, never exchanged);
// only the 512-float partial A^T u is all-reduced via DSMEM each iteration.

#define BS      32
#define M       256
#define N       512
#define CLUSTER 4
#define MLOC    (M / CLUSTER)   // 64
#define THREADS 512
#define ITERS   1000
#define ALPHA   0.02f
#define BETA    0.02f

// SMEM (floats): A_s[MLOC*N] | pv0[N] | pv1[N] | x_s[N] | y_s[N] | u_s[MLOC] | b_s[MLOC]
#define SMEM_FLOATS (MLOC*N + 2*N + N + N + MLOC + MLOC)
#define SMEM_BYTES  (SMEM_FLOATS * 4)

__device__ __forceinline__ uint32_t smem_u32(const void* p) {
    uint32_t a;
    asm("{ .reg .u64 t; cvta.to.shared.u64 t, %1; cvt.u32.u64 %0, t; }"
        : "=r"(a) : "l"(p));
    return a;
}

__device__ __forceinline__ void cluster_sync_() {
    asm volatile("barrier.cluster.arrive.aligned;" ::: "memory");
    asm volatile("barrier.cluster.wait.aligned;" ::: "memory");
}

extern "C" __global__ void __launch_bounds__(THREADS, 1) __cluster_dims__(CLUSTER, 1, 1)
pdhg_kernel(const float* __restrict__ Ag, const float* __restrict__ bg,
            float* __restrict__ out)
{
    extern __shared__ float smem_f[];
    float* A_s = smem_f;                  // MLOC*N
    float* pv0 = A_s + MLOC * N;          // N
    float* pv1 = pv0 + N;                 // N
    float* x_s = pv1 + N;                 // N
    float* y_s = x_s + N;                 // N
    float* u_s = y_s + N;                 // MLOC
    float* b_s = u_s + MLOC;              // MLOC

    const int tid  = threadIdx.x;
    const int warp = tid >> 5;
    const int lane = tid & 31;

    uint32_t rank;
    asm("mov.u32 %0, %%cluster_ctarank;" : "=r"(rank));
    const int batch = blockIdx.x / CLUSTER;

    const float* Abase = Ag + (size_t)batch * M * N + (size_t)rank * MLOC * N;

    // ---- Prologue: load A slice (64x512) into SMEM, coalesced float4 ----
    {
        const float4* Ain = (const float4*)Abase;
        float4* As4 = (float4*)A_s;
        #pragma unroll
        for (int k = 0; k < (MLOC * N / 4) / THREADS; k++)   // 16
            As4[tid + k * THREADS] = Ain[tid + k * THREADS];
    }
    if (tid < MLOC) {
        u_s[tid] = 0.0f;
        b_s[tid] = bg[batch * M + rank * MLOC + tid];
    }
    x_s[tid] = 0.0f;
    __syncthreads();

    // ---- Register-resident column copy: a[i] = A[row i][col tid] ----
    float a[MLOC];
    #pragma unroll
    for (int i = 0; i < MLOC; i++)
        a[i] = A_s[i * N + tid];

    // ---- Precompute DSMEM addresses of pv[buf][tid] on each cluster rank ----
    uint32_t ra[2][CLUSTER];
    {
        uint32_t la0 = smem_u32(pv0 + tid);
        uint32_t la1 = smem_u32(pv1 + tid);
        #pragma unroll
        for (int tr = 0; tr < CLUSTER; tr++) {
            asm("mapa.shared::cluster.u32 %0, %1, %2;"
                : "=r"(ra[0][tr]) : "r"(la0), "r"(tr));
            asm("mapa.shared::cluster.u32 %0, %1, %2;"
                : "=r"(ra[1][tr]) : "r"(la1), "r"(tr));
        }
    }

    int pb = 0;
    for (int it = 0; it < ITERS; it++) {
        // ---- Phase 1: pv[j] = sum_{i local} A[i][j] * u[i]   (regs + u bcast)
        float acc = 0.0f;
        #pragma unroll
        for (int i = 0; i < MLOC; i += 4) {
            float4 uu = *(const float4*)(u_s + i);
            acc = fmaf(a[i + 0], uu.x, acc);
            acc = fmaf(a[i + 1], uu.y, acc);
            acc = fmaf(a[i + 2], uu.z, acc);
            acc = fmaf(a[i + 3], uu.w, acc);
        }
        (pb ? pv1 : pv0)[tid] = acc;

        // ---- Cluster barrier: pv published (release) / peers visible (acquire)
        cluster_sync_();

        // ---- All-reduce pull: v = pv_rank0 + pv_rank1 + pv_rank2 + pv_rank3
        // (fixed rank order => bitwise-identical x on every CTA of the cluster)
        float v = 0.0f;
        #pragma unroll
        for (int tr = 0; tr < CLUSTER; tr++) {
            float p;
            asm volatile("ld.shared::cluster.f32 %0, [%1];"
                         : "=f"(p) : "r"(ra[pb][tr]));
            v += p;
        }

        // ---- x update + overrelaxed y ----
        float xo = x_s[tid];
        float z  = fmaf(-ALPHA, v, xo);
        float xn = fmaxf(z - ALPHA, 0.0f) - fmaxf(-z - ALPHA, 0.0f);
        x_s[tid] = xn;
        y_s[tid] = 2.0f * xn - xo;
        __syncthreads();

        // ---- Phase 3: w[i] = A[i][:] . y  for 4 local rows per warp ----
        const float4* y4 = (const float4*)y_s;
        float4 yv0 = y4[lane +  0];
        float4 yv1 = y4[lane + 32];
        float4 yv2 = y4[lane + 64];
        float4 yv3 = y4[lane + 96];

        #pragma unroll
        for (int rr = 0; rr < 4; rr++) {
            int i = warp * 4 + rr;
            const float4* Arow = (const float4*)(A_s + i * N);
            float4 a0 = Arow[lane +  0];
            float4 a1 = Arow[lane + 32];
            float4 a2 = Arow[lane + 64];
            float4 a3 = Arow[lane + 96];
            float s = 0.0f;
            s = fmaf(a0.x, yv0.x, s); s = fmaf(a0.y, yv0.y, s);
            s = fmaf(a0.z, yv0.z, s); s = fmaf(a0.w, yv0.w, s);
            s = fmaf(a1.x, yv1.x, s); s = fmaf(a1.y, yv1.y, s);
            s = fmaf(a1.z, yv1.z, s); s = fmaf(a1.w, yv1.w, s);
            s = fmaf(a2.x, yv2.x, s); s = fmaf(a2.y, yv2.y, s);
            s = fmaf(a2.z, yv2.z, s); s = fmaf(a2.w, yv2.w, s);
            s = fmaf(a3.x, yv3.x, s); s = fmaf(a3.y, yv3.y, s);
            s = fmaf(a3.z, yv3.z, s); s = fmaf(a3.w, yv3.w, s);
            #pragma unroll
            for (int off = 16; off > 0; off >>= 1)
                s += __shfl_xor_sync(0xFFFFFFFFu, s, off);
            if (lane == 0)
                u_s[i] = fmaf(BETA, s - b_s[i], u_s[i]);
        }
        __syncthreads();   // u_s ready for next phase 1
        pb ^= 1;
    }

    // No CTA may exit while a peer could still be reading its pv (last step d)
    cluster_sync_();

    if (rank == 0)
        out[batch * N + tid] = x_s[tid];
}

extern "C" void kernel_launch(void* const* d_in, const int* in_sizes, int n_in,
                              void* d_out, int out_size)
{
    (void)in_sizes; (void)n_in; (void)out_size;
    const float* A = (const float*)d_in[0];   // (32,256,512) f32
    const float* b = (const float*)d_in[1];   // (32,256)     f32
    float* out = (float*)d_out;               // (32,512)     f32

    static bool attr_set = false;
    // Setting the attribute is idempotent and not a stream op; safe every call.
    cudaFuncSetAttribute(pdhg_kernel,
                         cudaFuncAttributeMaxDynamicSharedMemorySize,
                         SMEM_BYTES);
    (void)attr_set;

    pdhg_kernel<<<BS * CLUSTER, THREADS, SMEM_BYTES>>>(A, b, out);
}

// round 7
// speedup vs baseline: 1.0024x; 1.0024x over previous
#include <cuda_runtime.h>
#include <cstdint>

// PDHG L1 solver: x = sh(x - a*A^T u, a); u += b*(A(2x_new - x_old) - b_vec)
// bs=32, m=256, n=512, iters=1000, alpha=beta=0.02
//
// Design: 32 clusters of 4 CTAs (one cluster per batch, 128 CTAs = 1 wave).
// Each CTA owns 64 rows of A: SMEM row-major copy (for A*y phase) + a
// register-resident column copy a[64] per thread (for A^T*u phase).
// u is partitioned across the cluster (64 entries per CTA, never exchanged);
// only the 512-float partial A^T u is all-reduced via DSMEM each iteration.

#define BS      32
#define M       256
#define N       512
#define CLUSTER 4
#define MLOC    (M / CLUSTER)   // 64
#define THREADS 512
#define ITERS   1000
#define ALPHA   0.02f
#define BETA    0.02f

// SMEM (floats): A_s[MLOC*N] | pv0[N] | pv1[N] | x_s[N] | y_s[N] | u_s[MLOC] | b_s[MLOC]
#define SMEM_FLOATS (MLOC*N + 2*N + N + N + MLOC + MLOC)
#define SMEM_BYTES  (SMEM_FLOATS * 4)

__device__ __forceinline__ uint32_t smem_u32(const void* p) {
    uint32_t a;
    asm("{ .reg .u64 t; cvta.to.shared.u64 t, %1; cvt.u32.u64 %0, t; }"
        : "=r"(a) : "l"(p));
    return a;
}

__device__ __forceinline__ void cluster_sync_() {
    asm volatile("barrier.cluster.arrive.aligned;" ::: "memory");
    asm volatile("barrier.cluster.wait.aligned;" ::: "memory");
}

extern "C" __global__ void __launch_bounds__(THREADS, 1) __cluster_dims__(CLUSTER, 1, 1)
pdhg_kernel(const float* __restrict__ Ag, const float* __restrict__ bg,
            float* __restrict__ out)
{
    extern __shared__ float smem_f[];
    float* A_s = smem_f;                  // MLOC*N
    float* pv0 = A_s + MLOC * N;          // N
    float* pv1 = pv0 + N;                 // N
    float* x_s = pv1 + N;                 // N
    float* y_s = x_s + N;                 // N
    float* u_s = y_s + N;                 // MLOC
    float* b_s = u_s + MLOC;              // MLOC

    const int tid  = threadIdx.x;
    const int warp = tid >> 5;
    const int lane = tid & 31;

    uint32_t rank;
    asm("mov.u32 %0, %%cluster_ctarank;" : "=r"(rank));
    const int batch = blockIdx.x / CLUSTER;

    const float* Abase = Ag + (size_t)batch * M * N + (size_t)rank * MLOC * N;

    // ---- Prologue: load A slice (64x512) into SMEM, coalesced float4 ----
    {
        const float4* Ain = (const float4*)Abase;
        float4* As4 = (float4*)A_s;
        #pragma unroll
        for (int k = 0; k < (MLOC * N / 4) / THREADS; k++)   // 16
            As4[tid + k * THREADS] = Ain[tid + k * THREADS];
    }
    if (tid < MLOC) {
        u_s[tid] = 0.0f;
        b_s[tid] = bg[batch * M + rank * MLOC + tid];
    }
    x_s[tid] = 0.0f;
    __syncthreads();

    // ---- Register-resident column copy: a[i] = A[row i][col tid] ----
    float a[MLOC];
    #pragma unroll
    for (int i = 0; i < MLOC; i++)
        a[i] = A_s[i * N + tid];

    // ---- Precompute DSMEM addresses of pv[buf][tid] on each cluster rank ----
    uint32_t ra[2][CLUSTER];
    {
        uint32_t la0 = smem_u32(pv0 + tid);
        uint32_t la1 = smem_u32(pv1 + tid);
        #pragma unroll
        for (int tr = 0; tr < CLUSTER; tr++) {
            asm("mapa.shared::cluster.u32 %0, %1, %2;"
                : "=r"(ra[0][tr]) : "r"(la0), "r"(tr));
            asm("mapa.shared::cluster.u32 %0, %1, %2;"
                : "=r"(ra[1][tr]) : "r"(la1), "r"(tr));
        }
    }

    int pb = 0;
    for (int it = 0; it < ITERS; it++) {
        // ---- Phase 1: pv[j] = sum_{i local} A[i][j] * u[i]   (regs + u bcast)
        float acc = 0.0f;
        #pragma unroll
        for (int i = 0; i < MLOC; i += 4) {
            float4 uu = *(const float4*)(u_s + i);
            acc = fmaf(a[i + 0], uu.x, acc);
            acc = fmaf(a[i + 1], uu.y, acc);
            acc = fmaf(a[i + 2], uu.z, acc);
            acc = fmaf(a[i + 3], uu.w, acc);
        }
        (pb ? pv1 : pv0)[tid] = acc;

        // ---- Cluster barrier: pv published (release) / peers visible (acquire)
        cluster_sync_();

        // ---- All-reduce pull: v = pv_rank0 + pv_rank1 + pv_rank2 + pv_rank3
        // (fixed rank order => bitwise-identical x on every CTA of the cluster)
        float v = 0.0f;
        #pragma unroll
        for (int tr = 0; tr < CLUSTER; tr++) {
            float p;
            asm volatile("ld.shared::cluster.f32 %0, [%1];"
                         : "=f"(p) : "r"(ra[pb][tr]));
            v += p;
        }

        // ---- x update + overrelaxed y ----
        float xo = x_s[tid];
        float z  = fmaf(-ALPHA, v, xo);
        float xn = fmaxf(z - ALPHA, 0.0f) - fmaxf(-z - ALPHA, 0.0f);
        x_s[tid] = xn;
        y_s[tid] = 2.0f * xn - xo;
        __syncthreads();

        // ---- Phase 3: w[i] = A[i][:] . y  for 4 local rows per warp ----
        const float4* y4 = (const float4*)y_s;
        float4 yv0 = y4[lane +  0];
        float4 yv1 = y4[lane + 32];
        float4 yv2 = y4[lane + 64];
        float4 yv3 = y4[lane + 96];

        #pragma unroll
        for (int rr = 0; rr < 4; rr++) {
            int i = warp * 4 + rr;
            const float4* Arow = (const float4*)(A_s + i * N);
            float4 a0 = Arow[lane +  0];
            float4 a1 = Arow[lane + 32];
            float4 a2 = Arow[lane + 64];
            float4 a3 = Arow[lane + 96];
            float s = 0.0f;
            s = fmaf(a0.x, yv0.x, s); s = fmaf(a0.y, yv0.y, s);
            s = fmaf(a0.z, yv0.z, s); s = fmaf(a0.w, yv0.w, s);
            s = fmaf(a1.x, yv1.x, s); s = fmaf(a1.y, yv1.y, s);
            s = fmaf(a1.z, yv1.z, s); s = fmaf(a1.w, yv1.w, s);
            s = fmaf(a2.x, yv2.x, s); s = fmaf(a2.y, yv2.y, s);
            s = fmaf(a2.z, yv2.z, s); s = fmaf(a2.w, yv2.w, s);
            s = fmaf(a3.x, yv3.x, s); s = fmaf(a3.y, yv3.y, s);
            s = fmaf(a3.z, yv3.z, s); s = fmaf(a3.w, yv3.w, s);
            #pragma unroll
            for (int off = 16; off > 0; off >>= 1)
                s += __shfl_xor_sync(0xFFFFFFFFu, s, off);
            if (lane == 0)
                u_s[i] = fmaf(BETA, s - b_s[i], u_s[i]);
        }
        __syncthreads();   // u_s ready for next phase 1
        pb ^= 1;
    }

    // No CTA may exit while a peer could still be reading its pv (last step d)
    cluster_sync_();

    if (rank == 0)
        out[batch * N + tid] = x_s[tid];
}

extern "C" void kernel_launch(void* const* d_in, const int* in_sizes, int n_in,
                              void* d_out, int out_size)
{
    (void)in_sizes; (void)n_in; (void)out_size;
    const float* A = (const float*)d_in[0];   // (32,256,512) f32
    const float* b = (const float*)d_in[1];   // (32,256)     f32
    float* out = (float*)d_out;               // (32,512)     f32

    static bool attr_set = false;
    // Setting the attribute is idempotent and not a stream op; safe every call.
    cudaFuncSetAttribute(pdhg_kernel,
                         cudaFuncAttributeMaxDynamicSharedMemorySize,
                         SMEM_BYTES);
    (void)attr_set;

    pdhg_kernel<<<BS * CLUSTER, THREADS, SMEM_BYTES>>>(A, b, out);
}